// round 13
// baseline (speedup 1.0000x reference)
#include <cuda_runtime.h>
#include <cuda_bf16.h>
#include <math.h>
#include <stdint.h>

// ---------------- scratch (no allocations allowed) ----------------
__device__ long long g_rowbase[2048];               // element offsets into x per (b,k)
__device__ float     g_score[2048];                 // attention scores, init v_b
__device__ __nv_bfloat16 g_A[2048u * 2304u];        // [Ah | Al | Ah] gathered x rows
__device__ __nv_bfloat16 g_B[768u * 2304u];         // [Bh | Bh | Bl], pool_W^T K-major
__device__ __nv_bfloat16 g_zA[128u * 2304u];        // [zh | zl | zh] pooled features
__device__ __nv_bfloat16 g_fcB[1024u * 2304u];      // [Fh | Fh | Fl], fc_w^T K-major (padded)

#define NEG_INF (-3.402823466e38f)

// ---------------- warp-MMA helpers (baseline PTX, works on sm_103) ----------------
__device__ __forceinline__ uint32_t smem_u32(const void* p) {
    uint32_t a;
    asm("{ .reg .u64 t; cvta.to.shared.u64 t, %1; cvt.u32.u64 %0, t; }"
        : "=r"(a) : "l"(p));
    return a;
}
__device__ __forceinline__ void ldsm_x4(uint32_t& r0, uint32_t& r1,
                                        uint32_t& r2, uint32_t& r3, uint32_t addr) {
    asm volatile("ldmatrix.sync.aligned.m8n8.x4.shared.b16 {%0,%1,%2,%3}, [%4];"
                 : "=r"(r0), "=r"(r1), "=r"(r2), "=r"(r3) : "r"(addr));
}
__device__ __forceinline__ void mma16816(float& c0, float& c1, float& c2, float& c3,
                                         uint32_t a0, uint32_t a1, uint32_t a2, uint32_t a3,
                                         uint32_t b0, uint32_t b1) {
    asm volatile("mma.sync.aligned.m16n8k16.row.col.f32.bf16.bf16.f32 "
                 "{%0,%1,%2,%3}, {%4,%5,%6,%7}, {%8,%9}, {%0,%1,%2,%3};"
                 : "+f"(c0), "+f"(c1), "+f"(c2), "+f"(c3)
                 : "r"(a0), "r"(a1), "r"(a2), "r"(a3), "r"(b0), "r"(b1));
}
#define CPA16(dst, src) \
    asm volatile("cp.async.cg.shared.global [%0], [%1], 16;" :: "r"(dst), "l"(src))
#define CPA_COMMIT() asm volatile("cp.async.commit_group;" ::: "memory")
#define CPA_WAIT(N)  asm volatile("cp.async.wait_group %0;" :: "n"(N) : "memory")

__device__ __forceinline__ void f2hilo(float x, __nv_bfloat16& h, __nv_bfloat16& l) {
    h = __float2bfloat16(x);
    l = __float2bfloat16(x - __bfloat162float(h));
}

// ---------------- kernel 1: topk+bias-init | convW | conv fcw ----------------
// blocks [0,128): per-batch top-16 of r + out=fc bias
// blocks [128,704): pool_W -> g_B  (576 = 24 k-tiles x 24 h-tiles)
// blocks [704,1472): fc_w -> g_fcB (768 = 24 k-tiles x 32 n-tiles, pad n>=1000 -> 0)
__global__ void __launch_bounds__(256) prep_kernel(
        const float* __restrict__ r, const float* __restrict__ vb,
        float* __restrict__ out, const float* __restrict__ fcb,
        const float* __restrict__ W, const float* __restrict__ fcw) {
    const int bid = blockIdx.x;
    const int t = threadIdx.x;

    if (bid >= 128) {
        __shared__ float tile[32][33];
        const int tx = t & 31, rt = t >> 5;    // 32 x 8
        if (bid < 704) {
            const int b2 = bid - 128;
            const int k0 = (b2 % 24) * 32, h0 = (b2 / 24) * 32;
#pragma unroll
            for (int i = 0; i < 4; i++)
                tile[rt + i * 8][tx] = W[(size_t)(k0 + rt + i * 8) * 768 + h0 + tx];
            __syncthreads();
#pragma unroll
            for (int i = 0; i < 4; i++) {
                const int h = h0 + rt + i * 8, k = k0 + tx;
                __nv_bfloat16 hi, lo;
                f2hilo(tile[tx][rt + i * 8], hi, lo);
                g_B[(size_t)h * 2304 + k]        = hi;
                g_B[(size_t)h * 2304 + 768 + k]  = hi;
                g_B[(size_t)h * 2304 + 1536 + k] = lo;
            }
        } else {
            const int b3 = bid - 704;
            const int k0 = (b3 % 24) * 32, n0 = (b3 / 24) * 32;
#pragma unroll
            for (int i = 0; i < 4; i++)
                tile[rt + i * 8][tx] = (n0 + tx < 1000)
                    ? fcw[(size_t)(k0 + rt + i * 8) * 1000 + n0 + tx] : 0.f;
            __syncthreads();
#pragma unroll
            for (int i = 0; i < 4; i++) {
                const int n = n0 + rt + i * 8, k = k0 + tx;
                __nv_bfloat16 hi, lo;
                f2hilo(tile[tx][rt + i * 8], hi, lo);
                g_fcB[(size_t)n * 2304 + k]        = hi;
                g_fcB[(size_t)n * 2304 + 768 + k]  = hi;
                g_fcB[(size_t)n * 2304 + 1536 + k] = lo;
            }
        }
        return;
    }

    // ---- topk + bias init ----
    const int b = bid;
    for (int n = t; n < 1000; n += 256) out[b * 1000 + n] = fcb[n];

    const int w = t >> 5, lane = t & 31;
    const float vbv = vb[0];
    float rv[16];
    const float* rp = r + b * 4096 + w * 512 + lane;
#pragma unroll
    for (int j = 0; j < 16; j++) rv[j] = rp[j * 32];

    __shared__ float cv[128];
    __shared__ int   ci[128];

    for (int it = 0; it < 16; it++) {
        float bv = rv[0]; int bs = 0;
#pragma unroll
        for (int j = 1; j < 16; j++)
            if (rv[j] > bv) { bv = rv[j]; bs = j; }
        int pay = (lane << 4) | bs;
#pragma unroll
        for (int off = 16; off; off >>= 1) {
            float ov = __shfl_xor_sync(0xffffffffu, bv, off);
            int   op = __shfl_xor_sync(0xffffffffu, pay, off);
            if (ov > bv || (ov == bv && op < pay)) { bv = ov; pay = op; }
        }
        if (lane == (pay >> 4)) {
            const int sl = pay & 15;
#pragma unroll
            for (int j = 0; j < 16; j++)
                if (sl == j) rv[j] = NEG_INF;
        }
        if (lane == 0) {
            cv[w * 16 + it] = bv;
            ci[w * 16 + it] = w * 512 + (pay >> 4) + (pay & 15) * 32;
        }
    }
    __syncthreads();

    if (w == 0) {
        float v4[4]; int i4[4];
#pragma unroll
        for (int j = 0; j < 4; j++) { v4[j] = cv[lane * 4 + j]; i4[j] = ci[lane * 4 + j]; }
        for (int it = 0; it < 16; it++) {
            float bv = v4[0]; int bs = 0;
#pragma unroll
            for (int j = 1; j < 4; j++)
                if (v4[j] > bv) { bv = v4[j]; bs = j; }
            int pay = (lane << 2) | bs;
#pragma unroll
            for (int off = 16; off; off >>= 1) {
                float ov = __shfl_xor_sync(0xffffffffu, bv, off);
                int   op = __shfl_xor_sync(0xffffffffu, pay, off);
                if (ov > bv || (ov == bv && op < pay)) { bv = ov; pay = op; }
            }
            const int slot = pay & 3, src = pay >> 2;
            if (lane == src) {
                if (slot == 0) v4[0] = NEG_INF;
                else if (slot == 1) v4[1] = NEG_INF;
                else if (slot == 2) v4[2] = NEG_INF;
                else v4[3] = NEG_INF;
            }
            const int myi = (slot == 0) ? i4[0] : (slot == 1) ? i4[1]
                          : (slot == 2) ? i4[2] : i4[3];
            const int idx = __shfl_sync(0xffffffffu, myi, src);
            if (lane == 0) {
                g_rowbase[b * 16 + it] = ((long long)b * 4096 + idx) * 768;
                g_score[b * 16 + it] = vbv;
            }
        }
    }
}

// ---------------- kernel 2: gathered x rows -> g_A = [Ah | Al | Ah] ----------------
__global__ void convX_kernel(const float* __restrict__ x) {
    const int b = blockIdx.x;     // 0..2047
    const int t = threadIdx.x;    // 192
    const float4 xv = *(const float4*)(x + g_rowbase[b] + t * 4);
    __nv_bfloat16 h0, h1, h2, h3, l0, l1, l2, l3;
    f2hilo(xv.x, h0, l0); f2hilo(xv.y, h1, l1);
    f2hilo(xv.z, h2, l2); f2hilo(xv.w, h3, l3);
    __nv_bfloat162 hh0, hh1, ll0, ll1;
    hh0.x = h0; hh0.y = h1; hh1.x = h2; hh1.y = h3;
    ll0.x = l0; ll0.y = l1; ll1.x = l2; ll1.y = l3;
    __nv_bfloat162* p0 = (__nv_bfloat162*)&g_A[(size_t)b * 2304 + t * 4];
    __nv_bfloat162* p1 = (__nv_bfloat162*)&g_A[(size_t)b * 2304 + 768 + t * 4];
    __nv_bfloat162* p2 = (__nv_bfloat162*)&g_A[(size_t)b * 2304 + 1536 + t * 4];
    p0[0] = hh0; p0[1] = hh1;
    p1[0] = ll0; p1[1] = ll1;
    p2[0] = hh0; p2[1] = hh1;
}

// ---------------- kernel 3: mma GEMM1 + tanh + v-dot epilogue ----------------
// Tile 64x64, BK=32, 128 thr / 4 warps (2m x 2n, warp tile 32x32),
// 3-stage cp.async pipeline. grid (12, 32) = 384 blocks.  [R10 config]
// NOTE: single __syncthreads per stage — the top-of-loop CPA_WAIT+sync of
// iteration s+1 orders all threads' compute on buffer s%3 before the issue
// into (s+3)%3 == s%3, so the trailing barrier is redundant.
static constexpr int G1_NS = 72;   // 2304/32

__global__ void __launch_bounds__(128) gemm1_mma(const float* __restrict__ Wb,
                                                 const float* __restrict__ v) {
    __shared__ __nv_bfloat16 As[3][64 * 40];
    __shared__ __nv_bfloat16 Bs[3][64 * 40];
    __shared__ float sWb[64], sv[64];

    const int t = threadIdx.x, lane = t & 31, w = t >> 5;
    const int wm = w & 1, wn = w >> 1;
    const int n0 = blockIdx.x * 64, m0 = blockIdx.y * 64;
    if (t < 64) { sWb[t] = Wb[n0 + t]; sv[t] = v[n0 + t]; }

    const int r0 = t >> 2, kc0 = (t & 3) * 8;     // rows r0, r0+32
    const uint32_t sA = smem_u32(As), sB = smem_u32(Bs);
    const uint32_t dOff = (uint32_t)(r0 * 40 + kc0) * 2u;

#define G1_ISSUE(S, BUF)                                                        \
    {                                                                           \
        const uint32_t dA = sA + (BUF) * 5120u + dOff;                          \
        const uint32_t dB = sB + (BUF) * 5120u + dOff;                          \
        CPA16(dA,         &g_A[(size_t)(m0 + r0) * 2304 + (S) * 32 + kc0]);     \
        CPA16(dA + 2560u, &g_A[(size_t)(m0 + r0 + 32) * 2304 + (S) * 32 + kc0]);\
        CPA16(dB,         &g_B[(size_t)(n0 + r0) * 2304 + (S) * 32 + kc0]);     \
        CPA16(dB + 2560u, &g_B[(size_t)(n0 + r0 + 32) * 2304 + (S) * 32 + kc0]);\
    }

    const uint32_t aoff = (uint32_t)((wm * 32 + (lane & 15)) * 40 + (lane >> 4) * 8) * 2u;
    const uint32_t boff = (uint32_t)((wn * 32 + (lane & 7) + (lane >> 4) * 8) * 40 +
                                     ((lane >> 3) & 1) * 8) * 2u;

    float acc[2][4][4];
#pragma unroll
    for (int i = 0; i < 2; i++)
#pragma unroll
        for (int j = 0; j < 4; j++)
#pragma unroll
            for (int c = 0; c < 4; c++) acc[i][j][c] = 0.f;

    G1_ISSUE(0, 0); CPA_COMMIT();
    G1_ISSUE(1, 1); CPA_COMMIT();

    for (int s = 0; s < G1_NS; s++) {
        const int buf = s % 3;
        CPA_WAIT(1);
        __syncthreads();
        if (s + 2 < G1_NS) { const int nb = (s + 2) % 3; G1_ISSUE(s + 2, nb); }
        CPA_COMMIT();

        const uint32_t ab = sA + (uint32_t)buf * 5120u;
        const uint32_t bb = sB + (uint32_t)buf * 5120u;
#pragma unroll
        for (int ks = 0; ks < 2; ks++) {
            uint32_t a[2][4], b2[4][2];
#pragma unroll
            for (int i = 0; i < 2; i++)
                ldsm_x4(a[i][0], a[i][1], a[i][2], a[i][3],
                        ab + aoff + (uint32_t)(i * 16 * 40 + ks * 16) * 2u);
#pragma unroll
            for (int jp = 0; jp < 2; jp++)
                ldsm_x4(b2[jp * 2][0], b2[jp * 2][1], b2[jp * 2 + 1][0], b2[jp * 2 + 1][1],
                        bb + boff + (uint32_t)(jp * 16 * 40 + ks * 16) * 2u);
#pragma unroll
            for (int i = 0; i < 2; i++)
#pragma unroll
                for (int j = 0; j < 4; j++)
                    mma16816(acc[i][j][0], acc[i][j][1], acc[i][j][2], acc[i][j][3],
                             a[i][0], a[i][1], a[i][2], a[i][3], b2[j][0], b2[j][1]);
        }
    }

    // epilogue: row = wm*32+i*16+lane/4 (+8 for c>=2), col = wn*32+(lane&3)*2+j*8+(c&1)
    const int cb = wn * 32 + (lane & 3) * 2;
#pragma unroll
    for (int i = 0; i < 2; i++) {
        float pA = 0.f, pB = 0.f;
#pragma unroll
        for (int j = 0; j < 4; j++) {
            const int n = cb + j * 8;
            pA += tanhf(acc[i][j][0] + sWb[n]) * sv[n] +
                  tanhf(acc[i][j][1] + sWb[n + 1]) * sv[n + 1];
            pB += tanhf(acc[i][j][2] + sWb[n]) * sv[n] +
                  tanhf(acc[i][j][3] + sWb[n + 1]) * sv[n + 1];
        }
        pA += __shfl_xor_sync(0xffffffffu, pA, 1);
        pA += __shfl_xor_sync(0xffffffffu, pA, 2);
        pB += __shfl_xor_sync(0xffffffffu, pB, 1);
        pB += __shfl_xor_sync(0xffffffffu, pB, 2);
        if ((lane & 3) == 0) {
            const int m = m0 + wm * 32 + i * 16 + (lane >> 2);
            atomicAdd(&g_score[m], pA);
            atomicAdd(&g_score[m + 8], pB);
        }
    }
}

// ---------------- kernel 4: softmax + z, emit z as [zh | zl | zh] ----------------
__global__ void __launch_bounds__(768) softz_kernel(const float* __restrict__ x) {
    __shared__ float s_al[16];
    __shared__ long long s_rb[16];

    const int b = blockIdx.x;
    const int t = threadIdx.x;

    if (t < 16) s_rb[t] = g_rowbase[b * 16 + t];
    if (t == 0) {
        float sc[16];
#pragma unroll
        for (int k = 0; k < 16; k++) sc[k] = g_score[b * 16 + k];
        float mx = sc[0];
#pragma unroll
        for (int k = 1; k < 16; k++) mx = fmaxf(mx, sc[k]);
        float sum = 0.f;
#pragma unroll
        for (int k = 0; k < 16; k++) { sc[k] = expf(sc[k] - mx); sum += sc[k]; }
        const float inv = 1.0f / sum;
#pragma unroll
        for (int k = 0; k < 16; k++) s_al[k] = sc[k] * inv;
    }
    __syncthreads();

    float z = 0.f;
#pragma unroll
    for (int k = 0; k < 16; k++) z += s_al[k] * x[s_rb[k] + t];

    __nv_bfloat16 h, l;
    f2hilo(z, h, l);
    g_zA[(size_t)b * 2304 + t]        = h;
    g_zA[(size_t)b * 2304 + 768 + t]  = l;
    g_zA[(size_t)b * 2304 + 1536 + t] = h;
}

// ---------------- kernel 5: fc via mma, split-K'x6, atomicAdd ----------------
// Tile 64x64, BK=32, 128 thr, grid (16, 2, 6); out pre-initialized with bias.
static constexpr int FC_NS = 12;   // 384/32

__global__ void __launch_bounds__(128) fc_mma(float* __restrict__ out) {
    __shared__ __nv_bfloat16 As[3][64 * 40];
    __shared__ __nv_bfloat16 Bs[3][64 * 40];

    const int t = threadIdx.x, lane = t & 31, w = t >> 5;
    const int wm = w & 1, wn = w >> 1;
    const int n0 = blockIdx.x * 64, m0 = blockIdx.y * 64;
    const int kb = blockIdx.z * 384;

    const int r0 = t >> 2, kc0 = (t & 3) * 8;
    const uint32_t sA = smem_u32(As), sB = smem_u32(Bs);
    const uint32_t dOff = (uint32_t)(r0 * 40 + kc0) * 2u;

#define FC_ISSUE(S, BUF)                                                             \
    {                                                                                \
        const uint32_t dA = sA + (BUF) * 5120u + dOff;                               \
        const uint32_t dB = sB + (BUF) * 5120u + dOff;                               \
        CPA16(dA,         &g_zA[(size_t)(m0 + r0) * 2304 + kb + (S) * 32 + kc0]);    \
        CPA16(dA + 2560u, &g_zA[(size_t)(m0 + r0 + 32) * 2304 + kb + (S) * 32 + kc0]);\
        CPA16(dB,         &g_fcB[(size_t)(n0 + r0) * 2304 + kb + (S) * 32 + kc0]);   \
        CPA16(dB + 2560u, &g_fcB[(size_t)(n0 + r0 + 32) * 2304 + kb + (S) * 32 + kc0]);\
    }

    const uint32_t aoff = (uint32_t)((wm * 32 + (lane & 15)) * 40 + (lane >> 4) * 8) * 2u;
    const uint32_t boff = (uint32_t)((wn * 32 + (lane & 7) + (lane >> 4) * 8) * 40 +
                                     ((lane >> 3) & 1) * 8) * 2u;

    float acc[2][4][4];
#pragma unroll
    for (int i = 0; i < 2; i++)
#pragma unroll
        for (int j = 0; j < 4; j++)
#pragma unroll
            for (int c = 0; c < 4; c++) acc[i][j][c] = 0.f;

    FC_ISSUE(0, 0); CPA_COMMIT();
    FC_ISSUE(1, 1); CPA_COMMIT();

    for (int s = 0; s < FC_NS; s++) {
        const int buf = s % 3;
        CPA_WAIT(1);
        __syncthreads();
        if (s + 2 < FC_NS) { const int nb = (s + 2) % 3; FC_ISSUE(s + 2, nb); }
        CPA_COMMIT();

        const uint32_t ab = sA + (uint32_t)buf * 5120u;
        const uint32_t bb = sB + (uint32_t)buf * 5120u;
#pragma unroll
        for (int ks = 0; ks < 2; ks++) {
            uint32_t a[2][4], b2[4][2];
#pragma unroll
            for (int i = 0; i < 2; i++)
                ldsm_x4(a[i][0], a[i][1], a[i][2], a[i][3],
                        ab + aoff + (uint32_t)(i * 16 * 40 + ks * 16) * 2u);
#pragma unroll
            for (int jp = 0; jp < 2; jp++)
                ldsm_x4(b2[jp * 2][0], b2[jp * 2][1], b2[jp * 2 + 1][0], b2[jp * 2 + 1][1],
                        bb + boff + (uint32_t)(jp * 16 * 40 + ks * 16) * 2u);
#pragma unroll
            for (int i = 0; i < 2; i++)
#pragma unroll
                for (int j = 0; j < 4; j++)
                    mma16816(acc[i][j][0], acc[i][j][1], acc[i][j][2], acc[i][j][3],
                             a[i][0], a[i][1], a[i][2], a[i][3], b2[j][0], b2[j][1]);
        }
    }

#pragma unroll
    for (int i = 0; i < 2; i++) {
        const int m = m0 + wm * 32 + i * 16 + (lane >> 2);
#pragma unroll
        for (int j = 0; j < 4; j++) {
            const int n = n0 + wn * 32 + (lane & 3) * 2 + j * 8;
            if (n < 1000) {
                atomicAdd(&out[m * 1000 + n], acc[i][j][0]);
                atomicAdd(&out[(m + 8) * 1000 + n], acc[i][j][2]);
            }
            if (n + 1 < 1000) {
                atomicAdd(&out[m * 1000 + n + 1], acc[i][j][1]);
                atomicAdd(&out[(m + 8) * 1000 + n + 1], acc[i][j][3]);
            }
        }
    }
}

// ---------------- launch ----------------
extern "C" void kernel_launch(void* const* d_in, const int* in_sizes, int n_in,
                              void* d_out, int out_size) {
    const float* x    = (const float*)d_in[0];   // [128,4096,768]
    const float* r    = (const float*)d_in[1];   // [128,4096]
    const float* pWw  = (const float*)d_in[2];   // [768,768]
    const float* pWb  = (const float*)d_in[3];   // [768]
    const float* pVw  = (const float*)d_in[4];   // [768,1]
    const float* pVb  = (const float*)d_in[5];   // [1]
    const float* fcw  = (const float*)d_in[6];   // [768,1000]
    const float* fcb  = (const float*)d_in[7];   // [1000]
    float* out = (float*)d_out;                  // [128,1000]

    prep_kernel<<<1472, 256>>>(r, pVb, out, fcb, pWw, fcw);
    convX_kernel<<<2048, 192>>>(x);
    gemm1_mma<<<dim3(12, 32), 128>>>(pWb, pVw);
    softz_kernel<<<128, 768>>>(x);
    fc_mma<<<dim3(16, 2, 6), 128>>>(out);
}

// round 15
// speedup vs baseline: 1.4418x; 1.4418x over previous
#include <cuda_runtime.h>
#include <cuda_bf16.h>
#include <math.h>
#include <stdint.h>

// ---------------- scratch (no allocations allowed) ----------------
__device__ long long g_rowbase[2048];               // element offsets into x per (b,k)
__device__ float     g_score[2048];                 // attention scores, init v_b
__device__ __nv_bfloat16 g_A[2048u * 2304u];        // [Ah | Al | Ah] gathered x rows
__device__ __nv_bfloat16 g_B[768u * 2304u];         // [Bh | Bh | Bl], pool_W^T K-major
__device__ __nv_bfloat16 g_zA[128u * 2304u];        // [zh | zl | zh] pooled features
__device__ __nv_bfloat16 g_fcB[1024u * 2304u];      // [Fh | Fh | Fl], fc_w^T K-major (padded)

#define NEG_INF (-3.402823466e38f)

// ---------------- warp-MMA helpers (baseline PTX, works on sm_103) ----------------
__device__ __forceinline__ uint32_t smem_u32(const void* p) {
    uint32_t a;
    asm("{ .reg .u64 t; cvta.to.shared.u64 t, %1; cvt.u32.u64 %0, t; }"
        : "=r"(a) : "l"(p));
    return a;
}
__device__ __forceinline__ void ldsm_x4(uint32_t& r0, uint32_t& r1,
                                        uint32_t& r2, uint32_t& r3, uint32_t addr) {
    asm volatile("ldmatrix.sync.aligned.m8n8.x4.shared.b16 {%0,%1,%2,%3}, [%4];"
                 : "=r"(r0), "=r"(r1), "=r"(r2), "=r"(r3) : "r"(addr));
}
__device__ __forceinline__ void mma16816(float& c0, float& c1, float& c2, float& c3,
                                         uint32_t a0, uint32_t a1, uint32_t a2, uint32_t a3,
                                         uint32_t b0, uint32_t b1) {
    asm volatile("mma.sync.aligned.m16n8k16.row.col.f32.bf16.bf16.f32 "
                 "{%0,%1,%2,%3}, {%4,%5,%6,%7}, {%8,%9}, {%0,%1,%2,%3};"
                 : "+f"(c0), "+f"(c1), "+f"(c2), "+f"(c3)
                 : "r"(a0), "r"(a1), "r"(a2), "r"(a3), "r"(b0), "r"(b1));
}
#define CPA16(dst, src) \
    asm volatile("cp.async.cg.shared.global [%0], [%1], 16;" :: "r"(dst), "l"(src))
#define CPA_COMMIT() asm volatile("cp.async.commit_group;" ::: "memory")
#define CPA_WAIT(N)  asm volatile("cp.async.wait_group %0;" :: "n"(N) : "memory")

__device__ __forceinline__ void f2hilo(float x, __nv_bfloat16& h, __nv_bfloat16& l) {
    h = __float2bfloat16(x);
    l = __float2bfloat16(x - __bfloat162float(h));
}

// ---------------- kernel 1: topk+bias-init | convW | conv fcw ----------------
// blocks [0,128): per-batch top-16 of r + out=fc bias
// blocks [128,704): pool_W -> g_B  (576 = 24 k-tiles x 24 h-tiles)
// blocks [704,1472): fc_w -> g_fcB (768 = 24 k-tiles x 32 n-tiles, pad n>=1000 -> 0)
__global__ void __launch_bounds__(256) prep_kernel(
        const float* __restrict__ r, const float* __restrict__ vb,
        float* __restrict__ out, const float* __restrict__ fcb,
        const float* __restrict__ W, const float* __restrict__ fcw) {
    const int bid = blockIdx.x;
    const int t = threadIdx.x;

    if (bid >= 128) {
        __shared__ float tile[32][33];
        const int tx = t & 31, rt = t >> 5;    // 32 x 8
        if (bid < 704) {
            const int b2 = bid - 128;
            const int k0 = (b2 % 24) * 32, h0 = (b2 / 24) * 32;
#pragma unroll
            for (int i = 0; i < 4; i++)
                tile[rt + i * 8][tx] = W[(size_t)(k0 + rt + i * 8) * 768 + h0 + tx];
            __syncthreads();
#pragma unroll
            for (int i = 0; i < 4; i++) {
                const int h = h0 + rt + i * 8, k = k0 + tx;
                __nv_bfloat16 hi, lo;
                f2hilo(tile[tx][rt + i * 8], hi, lo);
                g_B[(size_t)h * 2304 + k]        = hi;
                g_B[(size_t)h * 2304 + 768 + k]  = hi;
                g_B[(size_t)h * 2304 + 1536 + k] = lo;
            }
        } else {
            const int b3 = bid - 704;
            const int k0 = (b3 % 24) * 32, n0 = (b3 / 24) * 32;
#pragma unroll
            for (int i = 0; i < 4; i++)
                tile[rt + i * 8][tx] = (n0 + tx < 1000)
                    ? fcw[(size_t)(k0 + rt + i * 8) * 1000 + n0 + tx] : 0.f;
            __syncthreads();
#pragma unroll
            for (int i = 0; i < 4; i++) {
                const int n = n0 + rt + i * 8, k = k0 + tx;
                __nv_bfloat16 hi, lo;
                f2hilo(tile[tx][rt + i * 8], hi, lo);
                g_fcB[(size_t)n * 2304 + k]        = hi;
                g_fcB[(size_t)n * 2304 + 768 + k]  = hi;
                g_fcB[(size_t)n * 2304 + 1536 + k] = lo;
            }
        }
        return;
    }

    // ---- topk + bias init ----
    const int b = bid;
    for (int n = t; n < 1000; n += 256) out[b * 1000 + n] = fcb[n];

    const int w = t >> 5, lane = t & 31;
    const float vbv = vb[0];
    float rv[16];
    const float* rp = r + b * 4096 + w * 512 + lane;
#pragma unroll
    for (int j = 0; j < 16; j++) rv[j] = rp[j * 32];

    __shared__ float cv[128];
    __shared__ int   ci[128];

    for (int it = 0; it < 16; it++) {
        float bv = rv[0]; int bs = 0;
#pragma unroll
        for (int j = 1; j < 16; j++)
            if (rv[j] > bv) { bv = rv[j]; bs = j; }
        int pay = (lane << 4) | bs;
#pragma unroll
        for (int off = 16; off; off >>= 1) {
            float ov = __shfl_xor_sync(0xffffffffu, bv, off);
            int   op = __shfl_xor_sync(0xffffffffu, pay, off);
            if (ov > bv || (ov == bv && op < pay)) { bv = ov; pay = op; }
        }
        if (lane == (pay >> 4)) {
            const int sl = pay & 15;
#pragma unroll
            for (int j = 0; j < 16; j++)
                if (sl == j) rv[j] = NEG_INF;
        }
        if (lane == 0) {
            cv[w * 16 + it] = bv;
            ci[w * 16 + it] = w * 512 + (pay >> 4) + (pay & 15) * 32;
        }
    }
    __syncthreads();

    if (w == 0) {
        float v4[4]; int i4[4];
#pragma unroll
        for (int j = 0; j < 4; j++) { v4[j] = cv[lane * 4 + j]; i4[j] = ci[lane * 4 + j]; }
        for (int it = 0; it < 16; it++) {
            float bv = v4[0]; int bs = 0;
#pragma unroll
            for (int j = 1; j < 4; j++)
                if (v4[j] > bv) { bv = v4[j]; bs = j; }
            int pay = (lane << 2) | bs;
#pragma unroll
            for (int off = 16; off; off >>= 1) {
                float ov = __shfl_xor_sync(0xffffffffu, bv, off);
                int   op = __shfl_xor_sync(0xffffffffu, pay, off);
                if (ov > bv || (ov == bv && op < pay)) { bv = ov; pay = op; }
            }
            const int slot = pay & 3, src = pay >> 2;
            if (lane == src) {
                if (slot == 0) v4[0] = NEG_INF;
                else if (slot == 1) v4[1] = NEG_INF;
                else if (slot == 2) v4[2] = NEG_INF;
                else v4[3] = NEG_INF;
            }
            const int myi = (slot == 0) ? i4[0] : (slot == 1) ? i4[1]
                          : (slot == 2) ? i4[2] : i4[3];
            const int idx = __shfl_sync(0xffffffffu, myi, src);
            if (lane == 0) {
                g_rowbase[b * 16 + it] = ((long long)b * 4096 + idx) * 768;
                g_score[b * 16 + it] = vbv;
            }
        }
    }
}

// ---------------- kernel 2: gathered x rows -> g_A = [Ah | Al | Ah] ----------------
__global__ void convX_kernel(const float* __restrict__ x) {
    const int b = blockIdx.x;     // 0..2047
    const int t = threadIdx.x;    // 192
    const float4 xv = *(const float4*)(x + g_rowbase[b] + t * 4);
    __nv_bfloat16 h0, h1, h2, h3, l0, l1, l2, l3;
    f2hilo(xv.x, h0, l0); f2hilo(xv.y, h1, l1);
    f2hilo(xv.z, h2, l2); f2hilo(xv.w, h3, l3);
    __nv_bfloat162 hh0, hh1, ll0, ll1;
    hh0.x = h0; hh0.y = h1; hh1.x = h2; hh1.y = h3;
    ll0.x = l0; ll0.y = l1; ll1.x = l2; ll1.y = l3;
    __nv_bfloat162* p0 = (__nv_bfloat162*)&g_A[(size_t)b * 2304 + t * 4];
    __nv_bfloat162* p1 = (__nv_bfloat162*)&g_A[(size_t)b * 2304 + 768 + t * 4];
    __nv_bfloat162* p2 = (__nv_bfloat162*)&g_A[(size_t)b * 2304 + 1536 + t * 4];
    p0[0] = hh0; p0[1] = hh1;
    p1[0] = ll0; p1[1] = ll1;
    p2[0] = hh0; p2[1] = hh1;
}

// ---------------- kernel 3: mma GEMM1 + tanh + v-dot epilogue ----------------
// Tile 64x64, BK=32, 128 thr / 4 warps (2m x 2n, warp tile 32x32),
// 3-stage cp.async pipeline. grid (12, 32) = 384 blocks.  [R10 config, exact]
static constexpr int G1_NS = 72;   // 2304/32

__global__ void __launch_bounds__(128) gemm1_mma(const float* __restrict__ Wb,
                                                 const float* __restrict__ v) {
    __shared__ __nv_bfloat16 As[3][64 * 40];
    __shared__ __nv_bfloat16 Bs[3][64 * 40];
    __shared__ float sWb[64], sv[64];

    const int t = threadIdx.x, lane = t & 31, w = t >> 5;
    const int wm = w & 1, wn = w >> 1;
    const int n0 = blockIdx.x * 64, m0 = blockIdx.y * 64;
    if (t < 64) { sWb[t] = Wb[n0 + t]; sv[t] = v[n0 + t]; }

    const int r0 = t >> 2, kc0 = (t & 3) * 8;     // rows r0, r0+32
    const uint32_t sA = smem_u32(As), sB = smem_u32(Bs);
    const uint32_t dOff = (uint32_t)(r0 * 40 + kc0) * 2u;

#define G1_ISSUE(S, BUF)                                                        \
    {                                                                           \
        const uint32_t dA = sA + (BUF) * 5120u + dOff;                          \
        const uint32_t dB = sB + (BUF) * 5120u + dOff;                          \
        CPA16(dA,         &g_A[(size_t)(m0 + r0) * 2304 + (S) * 32 + kc0]);     \
        CPA16(dA + 2560u, &g_A[(size_t)(m0 + r0 + 32) * 2304 + (S) * 32 + kc0]);\
        CPA16(dB,         &g_B[(size_t)(n0 + r0) * 2304 + (S) * 32 + kc0]);     \
        CPA16(dB + 2560u, &g_B[(size_t)(n0 + r0 + 32) * 2304 + (S) * 32 + kc0]);\
    }

    const uint32_t aoff = (uint32_t)((wm * 32 + (lane & 15)) * 40 + (lane >> 4) * 8) * 2u;
    const uint32_t boff = (uint32_t)((wn * 32 + (lane & 7) + (lane >> 4) * 8) * 40 +
                                     ((lane >> 3) & 1) * 8) * 2u;

    float acc[2][4][4];
#pragma unroll
    for (int i = 0; i < 2; i++)
#pragma unroll
        for (int j = 0; j < 4; j++)
#pragma unroll
            for (int c = 0; c < 4; c++) acc[i][j][c] = 0.f;

    G1_ISSUE(0, 0); CPA_COMMIT();
    G1_ISSUE(1, 1); CPA_COMMIT();

    for (int s = 0; s < G1_NS; s++) {
        const int buf = s % 3;
        CPA_WAIT(1);
        __syncthreads();
        if (s + 2 < G1_NS) { const int nb = (s + 2) % 3; G1_ISSUE(s + 2, nb); }
        CPA_COMMIT();

        const uint32_t ab = sA + (uint32_t)buf * 5120u;
        const uint32_t bb = sB + (uint32_t)buf * 5120u;
#pragma unroll
        for (int ks = 0; ks < 2; ks++) {
            uint32_t a[2][4], b2[4][2];
#pragma unroll
            for (int i = 0; i < 2; i++)
                ldsm_x4(a[i][0], a[i][1], a[i][2], a[i][3],
                        ab + aoff + (uint32_t)(i * 16 * 40 + ks * 16) * 2u);
#pragma unroll
            for (int jp = 0; jp < 2; jp++)
                ldsm_x4(b2[jp * 2][0], b2[jp * 2][1], b2[jp * 2 + 1][0], b2[jp * 2 + 1][1],
                        bb + boff + (uint32_t)(jp * 16 * 40 + ks * 16) * 2u);
#pragma unroll
            for (int i = 0; i < 2; i++)
#pragma unroll
                for (int j = 0; j < 4; j++)
                    mma16816(acc[i][j][0], acc[i][j][1], acc[i][j][2], acc[i][j][3],
                             a[i][0], a[i][1], a[i][2], a[i][3], b2[j][0], b2[j][1]);
        }
        __syncthreads();
    }

    // epilogue: row = wm*32+i*16+lane/4 (+8 for c>=2), col = wn*32+(lane&3)*2+j*8+(c&1)
    const int cb = wn * 32 + (lane & 3) * 2;
#pragma unroll
    for (int i = 0; i < 2; i++) {
        float pA = 0.f, pB = 0.f;
#pragma unroll
        for (int j = 0; j < 4; j++) {
            const int n = cb + j * 8;
            pA += tanhf(acc[i][j][0] + sWb[n]) * sv[n] +
                  tanhf(acc[i][j][1] + sWb[n + 1]) * sv[n + 1];
            pB += tanhf(acc[i][j][2] + sWb[n]) * sv[n] +
                  tanhf(acc[i][j][3] + sWb[n + 1]) * sv[n + 1];
        }
        pA += __shfl_xor_sync(0xffffffffu, pA, 1);
        pA += __shfl_xor_sync(0xffffffffu, pA, 2);
        pB += __shfl_xor_sync(0xffffffffu, pB, 1);
        pB += __shfl_xor_sync(0xffffffffu, pB, 2);
        if ((lane & 3) == 0) {
            const int m = m0 + wm * 32 + i * 16 + (lane >> 2);
            atomicAdd(&g_score[m], pA);
            atomicAdd(&g_score[m + 8], pB);
        }
    }
}

// ---------------- kernel 4: softmax + z, emit z as [zh | zl | zh] ----------------
__global__ void __launch_bounds__(768) softz_kernel(const float* __restrict__ x) {
    __shared__ float s_al[16];
    __shared__ long long s_rb[16];

    const int b = blockIdx.x;
    const int t = threadIdx.x;

    if (t < 16) s_rb[t] = g_rowbase[b * 16 + t];
    if (t == 0) {
        float sc[16];
#pragma unroll
        for (int k = 0; k < 16; k++) sc[k] = g_score[b * 16 + k];
        float mx = sc[0];
#pragma unroll
        for (int k = 1; k < 16; k++) mx = fmaxf(mx, sc[k]);
        float sum = 0.f;
#pragma unroll
        for (int k = 0; k < 16; k++) { sc[k] = __expf(sc[k] - mx); sum += sc[k]; }
        const float inv = 1.0f / sum;
#pragma unroll
        for (int k = 0; k < 16; k++) s_al[k] = sc[k] * inv;
    }
    __syncthreads();

    float z = 0.f;
#pragma unroll
    for (int k = 0; k < 16; k++) z += s_al[k] * x[s_rb[k] + t];

    __nv_bfloat16 h, l;
    f2hilo(z, h, l);
    g_zA[(size_t)b * 2304 + t]        = h;
    g_zA[(size_t)b * 2304 + 768 + t]  = l;
    g_zA[(size_t)b * 2304 + 1536 + t] = h;
}

// ---------------- kernel 5: fc via mma, split-K'x6, atomicAdd ----------------
// Tile 64x64, BK=32, 128 thr, grid (16, 2, 6); out pre-initialized with bias.
static constexpr int FC_NS = 12;   // 384/32

__global__ void __launch_bounds__(128) fc_mma(float* __restrict__ out) {
    __shared__ __nv_bfloat16 As[3][64 * 40];
    __shared__ __nv_bfloat16 Bs[3][64 * 40];

    const int t = threadIdx.x, lane = t & 31, w = t >> 5;
    const int wm = w & 1, wn = w >> 1;
    const int n0 = blockIdx.x * 64, m0 = blockIdx.y * 64;
    const int kb = blockIdx.z * 384;

    const int r0 = t >> 2, kc0 = (t & 3) * 8;
    const uint32_t sA = smem_u32(As), sB = smem_u32(Bs);
    const uint32_t dOff = (uint32_t)(r0 * 40 + kc0) * 2u;

#define FC_ISSUE(S, BUF)                                                             \
    {                                                                                \
        const uint32_t dA = sA + (BUF) * 5120u + dOff;                               \
        const uint32_t dB = sB + (BUF) * 5120u + dOff;                               \
        CPA16(dA,         &g_zA[(size_t)(m0 + r0) * 2304 + kb + (S) * 32 + kc0]);    \
        CPA16(dA + 2560u, &g_zA[(size_t)(m0 + r0 + 32) * 2304 + kb + (S) * 32 + kc0]);\
        CPA16(dB,         &g_fcB[(size_t)(n0 + r0) * 2304 + kb + (S) * 32 + kc0]);   \
        CPA16(dB + 2560u, &g_fcB[(size_t)(n0 + r0 + 32) * 2304 + kb + (S) * 32 + kc0]);\
    }

    const uint32_t aoff = (uint32_t)((wm * 32 + (lane & 15)) * 40 + (lane >> 4) * 8) * 2u;
    const uint32_t boff = (uint32_t)((wn * 32 + (lane & 7) + (lane >> 4) * 8) * 40 +
                                     ((lane >> 3) & 1) * 8) * 2u;

    float acc[2][4][4];
#pragma unroll
    for (int i = 0; i < 2; i++)
#pragma unroll
        for (int j = 0; j < 4; j++)
#pragma unroll
            for (int c = 0; c < 4; c++) acc[i][j][c] = 0.f;

    FC_ISSUE(0, 0); CPA_COMMIT();
    FC_ISSUE(1, 1); CPA_COMMIT();

    for (int s = 0; s < FC_NS; s++) {
        const int buf = s % 3;
        CPA_WAIT(1);
        __syncthreads();
        if (s + 2 < FC_NS) { const int nb = (s + 2) % 3; FC_ISSUE(s + 2, nb); }
        CPA_COMMIT();

        const uint32_t ab = sA + (uint32_t)buf * 5120u;
        const uint32_t bb = sB + (uint32_t)buf * 5120u;
#pragma unroll
        for (int ks = 0; ks < 2; ks++) {
            uint32_t a[2][4], b2[4][2];
#pragma unroll
            for (int i = 0; i < 2; i++)
                ldsm_x4(a[i][0], a[i][1], a[i][2], a[i][3],
                        ab + aoff + (uint32_t)(i * 16 * 40 + ks * 16) * 2u);
#pragma unroll
            for (int jp = 0; jp < 2; jp++)
                ldsm_x4(b2[jp * 2][0], b2[jp * 2][1], b2[jp * 2 + 1][0], b2[jp * 2 + 1][1],
                        bb + boff + (uint32_t)(jp * 16 * 40 + ks * 16) * 2u);
#pragma unroll
            for (int i = 0; i < 2; i++)
#pragma unroll
                for (int j = 0; j < 4; j++)
                    mma16816(acc[i][j][0], acc[i][j][1], acc[i][j][2], acc[i][j][3],
                             a[i][0], a[i][1], a[i][2], a[i][3], b2[j][0], b2[j][1]);
        }
        __syncthreads();
    }

#pragma unroll
    for (int i = 0; i < 2; i++) {
        const int m = m0 + wm * 32 + i * 16 + (lane >> 2);
#pragma unroll
        for (int j = 0; j < 4; j++) {
            const int n = n0 + wn * 32 + (lane & 3) * 2 + j * 8;
            if (n < 1000) {
                atomicAdd(&out[m * 1000 + n], acc[i][j][0]);
                atomicAdd(&out[(m + 8) * 1000 + n], acc[i][j][2]);
            }
            if (n + 1 < 1000) {
                atomicAdd(&out[m * 1000 + n + 1], acc[i][j][1]);
                atomicAdd(&out[(m + 8) * 1000 + n + 1], acc[i][j][3]);
            }
        }
    }
}

// ---------------- launch ----------------
extern "C" void kernel_launch(void* const* d_in, const int* in_sizes, int n_in,
                              void* d_out, int out_size) {
    const float* x    = (const float*)d_in[0];   // [128,4096,768]
    const float* r    = (const float*)d_in[1];   // [128,4096]
    const float* pWw  = (const float*)d_in[2];   // [768,768]
    const float* pWb  = (const float*)d_in[3];   // [768]
    const float* pVw  = (const float*)d_in[4];   // [768,1]
    const float* pVb  = (const float*)d_in[5];   // [1]
    const float* fcw  = (const float*)d_in[6];   // [768,1000]
    const float* fcb  = (const float*)d_in[7];   // [1000]
    float* out = (float*)d_out;                  // [128,1000]

    prep_kernel<<<1472, 256>>>(r, pVb, out, fcb, pWw, fcw);
    convX_kernel<<<2048, 192>>>(x);
    gemm1_mma<<<dim3(12, 32), 128>>>(pWb, pVw);
    softz_kernel<<<128, 768>>>(x);
    fc_mma<<<dim3(16, 2, 6), 128>>>(out);
}

// round 16
// speedup vs baseline: 1.8124x; 1.2570x over previous
#include <cuda_runtime.h>
#include <cuda_bf16.h>
#include <cuda_fp16.h>
#include <math.h>
#include <stdint.h>

// ---------------- scratch (no allocations allowed) ----------------
__device__ long long g_rowbase[2048];               // element offsets into x per (b,k)
__device__ float     g_score[2048];                 // attention scores, init v_b
__device__ __half        g_A[2048u * 1536u];        // [Ah | Al] gathered x rows (fp16)
__device__ __half        g_B[768u * 1536u];         // [Bh | Bh], pool_W^T K-major (fp16)
__device__ __nv_bfloat16 g_zA[128u * 2304u];        // [zh | zl | zh] pooled features (bf16)
__device__ __nv_bfloat16 g_fcB[1024u * 2304u];      // [Fh | Fh | Fl], fc_w^T K-major (padded)

#define NEG_INF (-3.402823466e38f)

// ---------------- warp-MMA helpers (baseline PTX, works on sm_103) ----------------
__device__ __forceinline__ uint32_t smem_u32(const void* p) {
    uint32_t a;
    asm("{ .reg .u64 t; cvta.to.shared.u64 t, %1; cvt.u32.u64 %0, t; }"
        : "=r"(a) : "l"(p));
    return a;
}
__device__ __forceinline__ void ldsm_x4(uint32_t& r0, uint32_t& r1,
                                        uint32_t& r2, uint32_t& r3, uint32_t addr) {
    asm volatile("ldmatrix.sync.aligned.m8n8.x4.shared.b16 {%0,%1,%2,%3}, [%4];"
                 : "=r"(r0), "=r"(r1), "=r"(r2), "=r"(r3) : "r"(addr));
}
__device__ __forceinline__ void mma16816(float& c0, float& c1, float& c2, float& c3,
                                         uint32_t a0, uint32_t a1, uint32_t a2, uint32_t a3,
                                         uint32_t b0, uint32_t b1) {
    asm volatile("mma.sync.aligned.m16n8k16.row.col.f32.bf16.bf16.f32 "
                 "{%0,%1,%2,%3}, {%4,%5,%6,%7}, {%8,%9}, {%0,%1,%2,%3};"
                 : "+f"(c0), "+f"(c1), "+f"(c2), "+f"(c3)
                 : "r"(a0), "r"(a1), "r"(a2), "r"(a3), "r"(b0), "r"(b1));
}
__device__ __forceinline__ void mma16816h(float& c0, float& c1, float& c2, float& c3,
                                          uint32_t a0, uint32_t a1, uint32_t a2, uint32_t a3,
                                          uint32_t b0, uint32_t b1) {
    asm volatile("mma.sync.aligned.m16n8k16.row.col.f32.f16.f16.f32 "
                 "{%0,%1,%2,%3}, {%4,%5,%6,%7}, {%8,%9}, {%0,%1,%2,%3};"
                 : "+f"(c0), "+f"(c1), "+f"(c2), "+f"(c3)
                 : "r"(a0), "r"(a1), "r"(a2), "r"(a3), "r"(b0), "r"(b1));
}
#define CPA16(dst, src) \
    asm volatile("cp.async.cg.shared.global [%0], [%1], 16;" :: "r"(dst), "l"(src))
#define CPA_COMMIT() asm volatile("cp.async.commit_group;" ::: "memory")
#define CPA_WAIT(N)  asm volatile("cp.async.wait_group %0;" :: "n"(N) : "memory")

__device__ __forceinline__ void f2hilo(float x, __nv_bfloat16& h, __nv_bfloat16& l) {
    h = __float2bfloat16(x);
    l = __float2bfloat16(x - __bfloat162float(h));
}
__device__ __forceinline__ void f2hilo_h(float x, __half& h, __half& l) {
    h = __float2half_rn(x);
    l = __float2half_rn(x - __half2float(h));
}

// ---------------- kernel 1: topk+bias-init | convW (fp16) | conv fcw (bf16) ----------------
// blocks [0,128): per-batch top-16 of r + out=fc bias
// blocks [128,704): pool_W -> g_B  (576 = 24 k-tiles x 24 h-tiles), fp16 [Bh|Bh]
// blocks [704,1472): fc_w -> g_fcB (768 = 24 k-tiles x 32 n-tiles, pad n>=1000 -> 0)
__global__ void __launch_bounds__(256) prep_kernel(
        const float* __restrict__ r, const float* __restrict__ vb,
        float* __restrict__ out, const float* __restrict__ fcb,
        const float* __restrict__ W, const float* __restrict__ fcw) {
    const int bid = blockIdx.x;
    const int t = threadIdx.x;

    if (bid >= 128) {
        __shared__ float tile[32][33];
        const int tx = t & 31, rt = t >> 5;    // 32 x 8
        if (bid < 704) {
            const int b2 = bid - 128;
            const int k0 = (b2 % 24) * 32, h0 = (b2 / 24) * 32;
#pragma unroll
            for (int i = 0; i < 4; i++)
                tile[rt + i * 8][tx] = W[(size_t)(k0 + rt + i * 8) * 768 + h0 + tx];
            __syncthreads();
#pragma unroll
            for (int i = 0; i < 4; i++) {
                const int h = h0 + rt + i * 8, k = k0 + tx;
                const __half hi = __float2half_rn(tile[tx][rt + i * 8]);
                g_B[(size_t)h * 1536 + k]       = hi;
                g_B[(size_t)h * 1536 + 768 + k] = hi;
            }
        } else {
            const int b3 = bid - 704;
            const int k0 = (b3 % 24) * 32, n0 = (b3 / 24) * 32;
#pragma unroll
            for (int i = 0; i < 4; i++)
                tile[rt + i * 8][tx] = (n0 + tx < 1000)
                    ? fcw[(size_t)(k0 + rt + i * 8) * 1000 + n0 + tx] : 0.f;
            __syncthreads();
#pragma unroll
            for (int i = 0; i < 4; i++) {
                const int n = n0 + rt + i * 8, k = k0 + tx;
                __nv_bfloat16 hi, lo;
                f2hilo(tile[tx][rt + i * 8], hi, lo);
                g_fcB[(size_t)n * 2304 + k]        = hi;
                g_fcB[(size_t)n * 2304 + 768 + k]  = hi;
                g_fcB[(size_t)n * 2304 + 1536 + k] = lo;
            }
        }
        return;
    }

    // ---- topk + bias init ----
    const int b = bid;
    for (int n = t; n < 1000; n += 256) out[b * 1000 + n] = fcb[n];

    const int w = t >> 5, lane = t & 31;
    const float vbv = vb[0];
    float rv[16];
    const float* rp = r + b * 4096 + w * 512 + lane;
#pragma unroll
    for (int j = 0; j < 16; j++) rv[j] = rp[j * 32];

    __shared__ float cv[128];
    __shared__ int   ci[128];

    for (int it = 0; it < 16; it++) {
        float bv = rv[0]; int bs = 0;
#pragma unroll
        for (int j = 1; j < 16; j++)
            if (rv[j] > bv) { bv = rv[j]; bs = j; }
        int pay = (lane << 4) | bs;
#pragma unroll
        for (int off = 16; off; off >>= 1) {
            float ov = __shfl_xor_sync(0xffffffffu, bv, off);
            int   op = __shfl_xor_sync(0xffffffffu, pay, off);
            if (ov > bv || (ov == bv && op < pay)) { bv = ov; pay = op; }
        }
        if (lane == (pay >> 4)) {
            const int sl = pay & 15;
#pragma unroll
            for (int j = 0; j < 16; j++)
                if (sl == j) rv[j] = NEG_INF;
        }
        if (lane == 0) {
            cv[w * 16 + it] = bv;
            ci[w * 16 + it] = w * 512 + (pay >> 4) + (pay & 15) * 32;
        }
    }
    __syncthreads();

    if (w == 0) {
        float v4[4]; int i4[4];
#pragma unroll
        for (int j = 0; j < 4; j++) { v4[j] = cv[lane * 4 + j]; i4[j] = ci[lane * 4 + j]; }
        for (int it = 0; it < 16; it++) {
            float bv = v4[0]; int bs = 0;
#pragma unroll
            for (int j = 1; j < 4; j++)
                if (v4[j] > bv) { bv = v4[j]; bs = j; }
            int pay = (lane << 2) | bs;
#pragma unroll
            for (int off = 16; off; off >>= 1) {
                float ov = __shfl_xor_sync(0xffffffffu, bv, off);
                int   op = __shfl_xor_sync(0xffffffffu, pay, off);
                if (ov > bv || (ov == bv && op < pay)) { bv = ov; pay = op; }
            }
            const int slot = pay & 3, src = pay >> 2;
            if (lane == src) {
                if (slot == 0) v4[0] = NEG_INF;
                else if (slot == 1) v4[1] = NEG_INF;
                else if (slot == 2) v4[2] = NEG_INF;
                else v4[3] = NEG_INF;
            }
            const int myi = (slot == 0) ? i4[0] : (slot == 1) ? i4[1]
                          : (slot == 2) ? i4[2] : i4[3];
            const int idx = __shfl_sync(0xffffffffu, myi, src);
            if (lane == 0) {
                g_rowbase[b * 16 + it] = ((long long)b * 4096 + idx) * 768;
                g_score[b * 16 + it] = vbv;
            }
        }
    }
}

// ---------------- kernel 2: gathered x rows -> g_A = [Ah | Al] (fp16) ----------------
__global__ void convX_kernel(const float* __restrict__ x) {
    const int b = blockIdx.x;     // 0..2047
    const int t = threadIdx.x;    // 192
    const float4 xv = *(const float4*)(x + g_rowbase[b] + t * 4);
    __half h0, h1, h2, h3, l0, l1, l2, l3;
    f2hilo_h(xv.x, h0, l0); f2hilo_h(xv.y, h1, l1);
    f2hilo_h(xv.z, h2, l2); f2hilo_h(xv.w, h3, l3);
    __half2 hh0, hh1, ll0, ll1;
    hh0.x = h0; hh0.y = h1; hh1.x = h2; hh1.y = h3;
    ll0.x = l0; ll0.y = l1; ll1.x = l2; ll1.y = l3;
    __half2* p0 = (__half2*)&g_A[(size_t)b * 1536 + t * 4];
    __half2* p1 = (__half2*)&g_A[(size_t)b * 1536 + 768 + t * 4];
    p0[0] = hh0; p0[1] = hh1;
    p1[0] = ll0; p1[1] = ll1;
}

// ---------------- kernel 3: mma GEMM1 (fp16, K'=1536) + tanh + v-dot epilogue ----------------
// Tile 64x64, BK=32, 128 thr / 4 warps (2m x 2n, warp tile 32x32),
// 3-stage cp.async pipeline. grid (12, 32) = 384 blocks.
static constexpr int G1_NS = 48;   // 1536/32

__global__ void __launch_bounds__(128) gemm1_mma(const float* __restrict__ Wb,
                                                 const float* __restrict__ v) {
    __shared__ __half As[3][64 * 40];
    __shared__ __half Bs[3][64 * 40];
    __shared__ float sWb[64], sv[64];

    const int t = threadIdx.x, lane = t & 31, w = t >> 5;
    const int wm = w & 1, wn = w >> 1;
    const int n0 = blockIdx.x * 64, m0 = blockIdx.y * 64;
    if (t < 64) { sWb[t] = Wb[n0 + t]; sv[t] = v[n0 + t]; }

    const int r0 = t >> 2, kc0 = (t & 3) * 8;     // rows r0, r0+32
    const uint32_t sA = smem_u32(As), sB = smem_u32(Bs);
    const uint32_t dOff = (uint32_t)(r0 * 40 + kc0) * 2u;

#define G1_ISSUE(S, BUF)                                                        \
    {                                                                           \
        const uint32_t dA = sA + (BUF) * 5120u + dOff;                          \
        const uint32_t dB = sB + (BUF) * 5120u + dOff;                          \
        CPA16(dA,         &g_A[(size_t)(m0 + r0) * 1536 + (S) * 32 + kc0]);     \
        CPA16(dA + 2560u, &g_A[(size_t)(m0 + r0 + 32) * 1536 + (S) * 32 + kc0]);\
        CPA16(dB,         &g_B[(size_t)(n0 + r0) * 1536 + (S) * 32 + kc0]);     \
        CPA16(dB + 2560u, &g_B[(size_t)(n0 + r0 + 32) * 1536 + (S) * 32 + kc0]);\
    }

    const uint32_t aoff = (uint32_t)((wm * 32 + (lane & 15)) * 40 + (lane >> 4) * 8) * 2u;
    const uint32_t boff = (uint32_t)((wn * 32 + (lane & 7) + (lane >> 4) * 8) * 40 +
                                     ((lane >> 3) & 1) * 8) * 2u;

    float acc[2][4][4];
#pragma unroll
    for (int i = 0; i < 2; i++)
#pragma unroll
        for (int j = 0; j < 4; j++)
#pragma unroll
            for (int c = 0; c < 4; c++) acc[i][j][c] = 0.f;

    G1_ISSUE(0, 0); CPA_COMMIT();
    G1_ISSUE(1, 1); CPA_COMMIT();

    for (int s = 0; s < G1_NS; s++) {
        const int buf = s % 3;
        CPA_WAIT(1);
        __syncthreads();
        if (s + 2 < G1_NS) { const int nb = (s + 2) % 3; G1_ISSUE(s + 2, nb); }
        CPA_COMMIT();

        const uint32_t ab = sA + (uint32_t)buf * 5120u;
        const uint32_t bb = sB + (uint32_t)buf * 5120u;
#pragma unroll
        for (int ks = 0; ks < 2; ks++) {
            uint32_t a[2][4], b2[4][2];
#pragma unroll
            for (int i = 0; i < 2; i++)
                ldsm_x4(a[i][0], a[i][1], a[i][2], a[i][3],
                        ab + aoff + (uint32_t)(i * 16 * 40 + ks * 16) * 2u);
#pragma unroll
            for (int jp = 0; jp < 2; jp++)
                ldsm_x4(b2[jp * 2][0], b2[jp * 2][1], b2[jp * 2 + 1][0], b2[jp * 2 + 1][1],
                        bb + boff + (uint32_t)(jp * 16 * 40 + ks * 16) * 2u);
#pragma unroll
            for (int i = 0; i < 2; i++)
#pragma unroll
                for (int j = 0; j < 4; j++)
                    mma16816h(acc[i][j][0], acc[i][j][1], acc[i][j][2], acc[i][j][3],
                              a[i][0], a[i][1], a[i][2], a[i][3], b2[j][0], b2[j][1]);
        }
        __syncthreads();
    }

    // epilogue: row = wm*32+i*16+lane/4 (+8 for c>=2), col = wn*32+(lane&3)*2+j*8+(c&1)
    const int cb = wn * 32 + (lane & 3) * 2;
#pragma unroll
    for (int i = 0; i < 2; i++) {
        float pA = 0.f, pB = 0.f;
#pragma unroll
        for (int j = 0; j < 4; j++) {
            const int n = cb + j * 8;
            pA += tanhf(acc[i][j][0] + sWb[n]) * sv[n] +
                  tanhf(acc[i][j][1] + sWb[n + 1]) * sv[n + 1];
            pB += tanhf(acc[i][j][2] + sWb[n]) * sv[n] +
                  tanhf(acc[i][j][3] + sWb[n + 1]) * sv[n + 1];
        }
        pA += __shfl_xor_sync(0xffffffffu, pA, 1);
        pA += __shfl_xor_sync(0xffffffffu, pA, 2);
        pB += __shfl_xor_sync(0xffffffffu, pB, 1);
        pB += __shfl_xor_sync(0xffffffffu, pB, 2);
        if ((lane & 3) == 0) {
            const int m = m0 + wm * 32 + i * 16 + (lane >> 2);
            atomicAdd(&g_score[m], pA);
            atomicAdd(&g_score[m + 8], pB);
        }
    }
}

// ---------------- kernel 4: softmax + z, emit z as [zh | zl | zh] (bf16) ----------------
__global__ void __launch_bounds__(768) softz_kernel(const float* __restrict__ x) {
    __shared__ float s_al[16];
    __shared__ long long s_rb[16];

    const int b = blockIdx.x;
    const int t = threadIdx.x;

    if (t < 16) s_rb[t] = g_rowbase[b * 16 + t];
    if (t == 0) {
        float sc[16];
#pragma unroll
        for (int k = 0; k < 16; k++) sc[k] = g_score[b * 16 + k];
        float mx = sc[0];
#pragma unroll
        for (int k = 1; k < 16; k++) mx = fmaxf(mx, sc[k]);
        float sum = 0.f;
#pragma unroll
        for (int k = 0; k < 16; k++) { sc[k] = __expf(sc[k] - mx); sum += sc[k]; }
        const float inv = 1.0f / sum;
#pragma unroll
        for (int k = 0; k < 16; k++) s_al[k] = sc[k] * inv;
    }
    __syncthreads();

    float z = 0.f;
#pragma unroll
    for (int k = 0; k < 16; k++) z += s_al[k] * x[s_rb[k] + t];

    __nv_bfloat16 h, l;
    f2hilo(z, h, l);
    g_zA[(size_t)b * 2304 + t]        = h;
    g_zA[(size_t)b * 2304 + 768 + t]  = l;
    g_zA[(size_t)b * 2304 + 1536 + t] = h;
}

// ---------------- kernel 5: fc via mma (bf16 3-term), split-K'x6, atomicAdd ----------------
// Tile 64x64, BK=32, 128 thr, grid (16, 2, 6); out pre-initialized with bias.
static constexpr int FC_NS = 12;   // 384/32

__global__ void __launch_bounds__(128) fc_mma(float* __restrict__ out) {
    __shared__ __nv_bfloat16 As[3][64 * 40];
    __shared__ __nv_bfloat16 Bs[3][64 * 40];

    const int t = threadIdx.x, lane = t & 31, w = t >> 5;
    const int wm = w & 1, wn = w >> 1;
    const int n0 = blockIdx.x * 64, m0 = blockIdx.y * 64;
    const int kb = blockIdx.z * 384;

    const int r0 = t >> 2, kc0 = (t & 3) * 8;
    const uint32_t sA = smem_u32(As), sB = smem_u32(Bs);
    const uint32_t dOff = (uint32_t)(r0 * 40 + kc0) * 2u;

#define FC_ISSUE(S, BUF)                                                             \
    {                                                                                \
        const uint32_t dA = sA + (BUF) * 5120u + dOff;                               \
        const uint32_t dB = sB + (BUF) * 5120u + dOff;                               \
        CPA16(dA,         &g_zA[(size_t)(m0 + r0) * 2304 + kb + (S) * 32 + kc0]);    \
        CPA16(dA + 2560u, &g_zA[(size_t)(m0 + r0 + 32) * 2304 + kb + (S) * 32 + kc0]);\
        CPA16(dB,         &g_fcB[(size_t)(n0 + r0) * 2304 + kb + (S) * 32 + kc0]);   \
        CPA16(dB + 2560u, &g_fcB[(size_t)(n0 + r0 + 32) * 2304 + kb + (S) * 32 + kc0]);\
    }

    const uint32_t aoff = (uint32_t)((wm * 32 + (lane & 15)) * 40 + (lane >> 4) * 8) * 2u;
    const uint32_t boff = (uint32_t)((wn * 32 + (lane & 7) + (lane >> 4) * 8) * 40 +
                                     ((lane >> 3) & 1) * 8) * 2u;

    float acc[2][4][4];
#pragma unroll
    for (int i = 0; i < 2; i++)
#pragma unroll
        for (int j = 0; j < 4; j++)
#pragma unroll
            for (int c = 0; c < 4; c++) acc[i][j][c] = 0.f;

    FC_ISSUE(0, 0); CPA_COMMIT();
    FC_ISSUE(1, 1); CPA_COMMIT();

    for (int s = 0; s < FC_NS; s++) {
        const int buf = s % 3;
        CPA_WAIT(1);
        __syncthreads();
        if (s + 2 < FC_NS) { const int nb = (s + 2) % 3; FC_ISSUE(s + 2, nb); }
        CPA_COMMIT();

        const uint32_t ab = sA + (uint32_t)buf * 5120u;
        const uint32_t bb = sB + (uint32_t)buf * 5120u;
#pragma unroll
        for (int ks = 0; ks < 2; ks++) {
            uint32_t a[2][4], b2[4][2];
#pragma unroll
            for (int i = 0; i < 2; i++)
                ldsm_x4(a[i][0], a[i][1], a[i][2], a[i][3],
                        ab + aoff + (uint32_t)(i * 16 * 40 + ks * 16) * 2u);
#pragma unroll
            for (int jp = 0; jp < 2; jp++)
                ldsm_x4(b2[jp * 2][0], b2[jp * 2][1], b2[jp * 2 + 1][0], b2[jp * 2 + 1][1],
                        bb + boff + (uint32_t)(jp * 16 * 40 + ks * 16) * 2u);
#pragma unroll
            for (int i = 0; i < 2; i++)
#pragma unroll
                for (int j = 0; j < 4; j++)
                    mma16816(acc[i][j][0], acc[i][j][1], acc[i][j][2], acc[i][j][3],
                             a[i][0], a[i][1], a[i][2], a[i][3], b2[j][0], b2[j][1]);
        }
        __syncthreads();
    }

#pragma unroll
    for (int i = 0; i < 2; i++) {
        const int m = m0 + wm * 32 + i * 16 + (lane >> 2);
#pragma unroll
        for (int j = 0; j < 4; j++) {
            const int n = n0 + wn * 32 + (lane & 3) * 2 + j * 8;
            if (n < 1000) {
                atomicAdd(&out[m * 1000 + n], acc[i][j][0]);
                atomicAdd(&out[(m + 8) * 1000 + n], acc[i][j][2]);
            }
            if (n + 1 < 1000) {
                atomicAdd(&out[m * 1000 + n + 1], acc[i][j][1]);
                atomicAdd(&out[(m + 8) * 1000 + n + 1], acc[i][j][3]);
            }
        }
    }
}

// ---------------- launch ----------------
extern "C" void kernel_launch(void* const* d_in, const int* in_sizes, int n_in,
                              void* d_out, int out_size) {
    const float* x    = (const float*)d_in[0];   // [128,4096,768]
    const float* r    = (const float*)d_in[1];   // [128,4096]
    const float* pWw  = (const float*)d_in[2];   // [768,768]
    const float* pWb  = (const float*)d_in[3];   // [768]
    const float* pVw  = (const float*)d_in[4];   // [768,1]
    const float* pVb  = (const float*)d_in[5];   // [1]
    const float* fcw  = (const float*)d_in[6];   // [768,1000]
    const float* fcb  = (const float*)d_in[7];   // [1000]
    float* out = (float*)d_out;                  // [128,1000]

    prep_kernel<<<1472, 256>>>(r, pVb, out, fcb, pWw, fcw);
    convX_kernel<<<2048, 192>>>(x);
    gemm1_mma<<<dim3(12, 32), 128>>>(pWb, pVw);
    softz_kernel<<<128, 768>>>(x);
    fc_mma<<<dim3(16, 2, 6), 128>>>(out);
}